// round 9
// baseline (speedup 1.0000x reference)
#include <cuda_runtime.h>
#include <cuda_fp16.h>

// ---------------------------------------------------------------------------
// KPlaneRBFField on GB300 — round 6.
//  memset:  g_hist = 0 (graph memset node).
//  k1 prep: transpose 9 planes [32,r,r] -> fp16 [r,r,32] + lc0 -> fp16
//           + Morton histogram (hist folded in; field is now launch #4).
//  k2 scan1: parallel scan (32 blocks).
//  k3 scatter: writes SORTED (xs0,xs1,xs2,pid) float4.
//  k4 field: 8 pts/warp; batched 12-load plane sampling per scale (MLP),
//           batched RBF loads, __stcs streaming output stores (protect L2).
// ---------------------------------------------------------------------------

#define NSIDE 64
#define MAXN  524288
#define NBUCK 32768
#define TP_POS 128

__device__ __half   g_planesTh[33030144];  // 66 MB transposed fp16 planes
__device__ __half   g_lc0h[8388608];       // 16.5 MB fp16 codes
__device__ unsigned g_hist[NBUCK];
__device__ unsigned g_blksum[32];
__device__ unsigned g_key[MAXN];
__device__ float4   g_spts[MAXN];          // sorted (xs0,xs1,xs2,pid)

__constant__ int c_plane_off[9] = {
    0,        524288,   1048576,
    1572864,  3670016,  5767168,
    7864320,  16252928, 24641536
};
__constant__ int c_blkCum[10] = {0,128,256,384,896,1408,1920,3968,6016,8064};
__constant__ int c_res[9]     = {128,128,128,256,256,256,512,512,512};

struct PrepArgs {
    const float* p[9];
    const float* lc0;
    const float* pts;
    const float* aabb;
    int n;
};

__device__ __forceinline__ unsigned spread3(unsigned x)
{
    x &= 0x3FF;
    x = (x | (x << 16)) & 0x30000FF;
    x = (x | (x << 8))  & 0x300F00F;
    x = (x | (x << 4))  & 0x30C30C3;
    x = (x | (x << 2))  & 0x9249249;
    return x;
}

// ---------------- k1: transpose + lc0 convert + histogram -------------------
__global__ void __launch_bounds__(256) prep_kernel(PrepArgs a)
{
    int b = blockIdx.x;
    int tid = threadIdx.x;

    if (b >= 16256) {                       // Morton histogram
        int i = (b - 16256) * 256 + tid;
        if (i >= a.n) return;
        float a0x = a.aabb[0], a0y = a.aabb[1], a0z = a.aabb[2];
        float a1x = a.aabb[3], a1y = a.aabb[4], a1z = a.aabb[5];
        float x = (a.pts[3 * i + 0] - a0x) * (2.0f / (a1x - a0x)) - 1.0f;
        float y = (a.pts[3 * i + 1] - a0y) * (2.0f / (a1y - a0y)) - 1.0f;
        float z = (a.pts[3 * i + 2] - a0z) * (2.0f / (a1z - a0z)) - 1.0f;
        int qx = min(max((int)((x + 1.0f) * 16.0f), 0), 31);
        int qy = min(max((int)((y + 1.0f) * 16.0f), 0), 31);
        int qz = min(max((int)((z + 1.0f) * 16.0f), 0), 31);
        unsigned key = (spread3(qx) << 2) | (spread3(qy) << 1) | spread3(qz);
        g_key[i] = key;
        atomicAdd(&g_hist[key], 1u);
        return;
    }
    if (b >= 8064) {                        // lc0 convert
        int i = (b - 8064) * 256 + tid;
        float4 v = __ldg((const float4*)a.lc0 + i);
        __half2 h0 = __floats2half2_rn(v.x, v.y);
        __half2 h1 = __floats2half2_rn(v.z, v.w);
        ((uint2*)g_lc0h)[i] = make_uint2(*(unsigned*)&h0, *(unsigned*)&h1);
        return;
    }

    // plane transpose
    __shared__ float tile[TP_POS][33];
    int pi = 0;
    #pragma unroll
    for (int i = 1; i < 9; i++) pi += (b >= c_blkCum[i]) ? 1 : 0;
    int r  = c_res[pi];
    int rr = r * r;
    int posBase = (b - c_blkCum[pi]) * TP_POS;
    const float4* src4 = (const float4*)a.p[pi];
    int rr4 = rr >> 2;
    int pb4 = posBase >> 2;

    #pragma unroll
    for (int it = 0; it < 4; it++) {
        int v  = tid + it * 256;
        int ch = v >> 5;
        int pv = v & 31;
        float4 val = src4[ch * rr4 + pb4 + pv];
        int p = pv << 2;
        tile[p + 0][ch] = val.x;
        tile[p + 1][ch] = val.y;
        tile[p + 2][ch] = val.z;
        tile[p + 3][ch] = val.w;
    }
    __syncthreads();

    uint2* dst2 = (uint2*)(g_planesTh + c_plane_off[pi]) + posBase * 8;
    #pragma unroll
    for (int it = 0; it < 4; it++) {
        int v  = tid + it * 256;
        int p  = v >> 3;
        int c4 = (v & 7) << 2;
        __half2 h0 = __floats2half2_rn(tile[p][c4 + 0], tile[p][c4 + 1]);
        __half2 h1 = __floats2half2_rn(tile[p][c4 + 2], tile[p][c4 + 3]);
        dst2[v] = make_uint2(*(unsigned*)&h0, *(unsigned*)&h1);
    }
}

// ---------------- k2: scan ---------------------------------------------------
__global__ void __launch_bounds__(1024) scan1_kernel()
{
    __shared__ unsigned wsum[32];
    int t = threadIdx.x;
    int lane = t & 31;
    int wid = t >> 5;
    int i = blockIdx.x * 1024 + t;
    unsigned v = g_hist[i];

    unsigned x = v;
    #pragma unroll
    for (int off = 1; off < 32; off <<= 1) {
        unsigned y = __shfl_up_sync(0xFFFFFFFFu, x, off);
        if (lane >= off) x += y;
    }
    if (lane == 31) wsum[wid] = x;
    __syncthreads();
    if (wid == 0) {
        unsigned w = wsum[lane];
        unsigned ww = w;
        #pragma unroll
        for (int off = 1; off < 32; off <<= 1) {
            unsigned y = __shfl_up_sync(0xFFFFFFFFu, ww, off);
            if (lane >= off) ww += y;
        }
        wsum[lane] = ww - w;
        if (lane == 31) g_blksum[blockIdx.x] = ww;
    }
    __syncthreads();
    g_hist[i] = x + wsum[wid] - v;
}

// ---------------- k3: scatter -------------------------------------------------
__global__ void scatter_kernel(const float* __restrict__ pts,
                               const float* __restrict__ aabb, int n)
{
    __shared__ unsigned blkoff[32];
    int t = threadIdx.x;
    if (t < 32) {
        unsigned v = g_blksum[t];
        unsigned x = v;
        #pragma unroll
        for (int off = 1; off < 32; off <<= 1) {
            unsigned y = __shfl_up_sync(0xFFFFFFFFu, x, off);
            if (t >= off) x += y;
        }
        blkoff[t] = x - v;
    }
    __syncthreads();

    int i = blockIdx.x * blockDim.x + t;
    if (i >= n) return;
    unsigned key = g_key[i];
    unsigned pos = atomicAdd(&g_hist[key], 1u) + blkoff[key >> 10];

    float a0x = aabb[0], a0y = aabb[1], a0z = aabb[2];
    float a1x = aabb[3], a1y = aabb[4], a1z = aabb[5];
    float xs0 = (pts[3 * i + 0] - a0x) * (2.0f / (a1x - a0x)) - 1.0f;
    float xs1 = (pts[3 * i + 1] - a0y) * (2.0f / (a1y - a0y)) - 1.0f;
    float xs2 = (pts[3 * i + 2] - a0z) * (2.0f / (a1z - a0z)) - 1.0f;
    g_spts[pos] = make_float4(xs0, xs1, xs2, __int_as_float(i));
}

__global__ void ident_kernel(const float* __restrict__ pts,
                             const float* __restrict__ aabb, int n)
{
    int i = blockIdx.x * blockDim.x + threadIdx.x;
    if (i >= n) return;
    float a0x = aabb[0], a0y = aabb[1], a0z = aabb[2];
    float a1x = aabb[3], a1y = aabb[4], a1z = aabb[5];
    float xs0 = (pts[3 * i + 0] - a0x) * (2.0f / (a1x - a0x)) - 1.0f;
    float xs1 = (pts[3 * i + 1] - a0y) * (2.0f / (a1y - a0y)) - 1.0f;
    float xs2 = (pts[3 * i + 2] - a0z) * (2.0f / (a1z - a0z)) - 1.0f;
    g_spts[i] = make_float4(xs0, xs1, xs2, __int_as_float(i));
}

// ---------------- fp16 helpers ----------------------------------------------
__device__ __forceinline__ void h8tof8(uint4 u, float* f)
{
    float2 p;
    p = __half22float2(*(const __half2*)&u.x); f[0] = p.x; f[1] = p.y;
    p = __half22float2(*(const __half2*)&u.y); f[2] = p.x; f[3] = p.y;
    p = __half22float2(*(const __half2*)&u.z); f[4] = p.x; f[5] = p.y;
    p = __half22float2(*(const __half2*)&u.w); f[6] = p.x; f[7] = p.y;
}

struct SCtx { const uint4* b; int rs; float wx, wy; };

__device__ __forceinline__ SCtx mkctx(const __half* __restrict__ T, int r,
                                      float u, float v, int c8)
{
    float fr = (float)(r - 1);
    float fx = (u + 1.0f) * 0.5f * fr;
    float fy = (v + 1.0f) * 0.5f * fr;
    float flx = fminf(fmaxf(floorf(fx), 0.0f), (float)(r - 2));
    float fly = fminf(fmaxf(floorf(fy), 0.0f), (float)(r - 2));
    SCtx c;
    c.wx = fx - flx;
    c.wy = fy - fly;
    int ix = (int)flx;
    int iy = (int)fly;
    c.b  = (const uint4*)(T + ((iy * r + ix) << 5)) + c8;
    c.rs = r << 2;
    return c;
}

__device__ __forceinline__ void lerp8(uint4 a00, uint4 a01, uint4 a10, uint4 a11,
                                      float wx, float wy, float* o)
{
    float f00[8], f01[8], f10[8], f11[8];
    h8tof8(a00, f00); h8tof8(a01, f01); h8tof8(a10, f10); h8tof8(a11, f11);
    #pragma unroll
    for (int k = 0; k < 8; k++) {
        float t0 = f00[k] + (f01[k] - f00[k]) * wx;
        float t1 = f10[k] + (f11[k] - f10[k]) * wx;
        o[k] = t0 + (t1 - t0) * wy;
    }
}

// ---------------- k4: field kernel: 8 pts/warp --------------------------------
__global__ void __launch_bounds__(256) field_kernel(
    const float* __restrict__ ks,
    const float* __restrict__ kpb,
    float* __restrict__ out,
    int npts)
{
    int gwarp = (int)((blockIdx.x * blockDim.x + threadIdx.x) >> 5);
    int lane  = threadIdx.x & 31;
    int pslot = lane >> 2;
    int c8    = lane & 3;

    int slot = gwarp * 8 + pslot;
    if (slot >= npts) return;

    float4 sp = __ldg(&g_spts[slot]);
    float xs0 = sp.x, xs1 = sp.y, xs2 = sp.z;
    int pid = __float_as_int(sp.w);

    float* outP = out + (size_t)pid * 128;
    const float4* kpb4 = (const float4*)kpb;

    const int resArr[3] = {128, 256, 512};
    #pragma unroll
    for (int s = 0; s < 3; s++) {
        int r = resArr[s];
        SCtx c0 = mkctx(g_planesTh + c_plane_off[s * 3 + 0], r, xs0, xs1, c8);
        SCtx c1 = mkctx(g_planesTh + c_plane_off[s * 3 + 1], r, xs0, xs2, c8);
        SCtx c2 = mkctx(g_planesTh + c_plane_off[s * 3 + 2], r, xs1, xs2, c8);
        // batch all 12 loads (MLP=12) before converting
        uint4 a00 = __ldg(c0.b),            a01 = __ldg(c0.b + 4);
        uint4 a10 = __ldg(c0.b + c0.rs),    a11 = __ldg(c0.b + c0.rs + 4);
        uint4 b00 = __ldg(c1.b),            b01 = __ldg(c1.b + 4);
        uint4 b10 = __ldg(c1.b + c1.rs),    b11 = __ldg(c1.b + c1.rs + 4);
        uint4 d00 = __ldg(c2.b),            d01 = __ldg(c2.b + 4);
        uint4 d10 = __ldg(c2.b + c2.rs),    d11 = __ldg(c2.b + c2.rs + 4);
        float f0[8], f1[8], f2[8];
        lerp8(a00, a01, a10, a11, c0.wx, c0.wy, f0);
        lerp8(b00, b01, b10, b11, c1.wx, c1.wy, f1);
        lerp8(d00, d01, d10, d11, c2.wx, c2.wy, f2);
        float4 bb0 = __ldg(kpb4 + s * 8 + c8 * 2);
        float4 bb1 = __ldg(kpb4 + s * 8 + c8 * 2 + 1);
        float4 o0, o1;
        o0.x = f0[0] * f1[0] * f2[0] + bb0.x;
        o0.y = f0[1] * f1[1] * f2[1] + bb0.y;
        o0.z = f0[2] * f1[2] * f2[2] + bb0.z;
        o0.w = f0[3] * f1[3] * f2[3] + bb0.w;
        o1.x = f0[4] * f1[4] * f2[4] + bb1.x;
        o1.y = f0[5] * f1[5] * f2[5] + bb1.y;
        o1.z = f0[6] * f1[6] * f2[6] + bb1.z;
        o1.w = f0[7] * f1[7] * f2[7] + bb1.w;
        float* op = outP + s * 32 + (c8 << 3);
        __stcs((float4*)op, o0);           // streaming: don't pollute L2
        __stcs((float4*)(op + 4), o1);
    }

    // ---- RBF features over 64^3 grid on [-1,1]
    const float interval = 2.0f / (float)(NSIDE - 1);
    float c0f = fminf(fmaxf(floorf((xs0 + 1.0f) / interval), 0.0f), (float)(NSIDE - 2));
    float c1f = fminf(fmaxf(floorf((xs1 + 1.0f) / interval), 0.0f), (float)(NSIDE - 2));
    float c2f = fminf(fmaxf(floorf((xs2 + 1.0f) / interval), 0.0f), (float)(NSIDE - 2));
    int ci0 = (int)c0f, ci1 = (int)c1f, ci2 = (int)c2f;

    // batch all index computation + loads
    int idxA[8];
    float d2A[8];
    #pragma unroll
    for (int k = 0; k < 8; k++) {
        int i0 = ci0 + ((k >> 2) & 1);
        int i1 = ci1 + ((k >> 1) & 1);
        int i2 = ci2 + (k & 1);
        idxA[k] = (i0 * NSIDE + i1) * NSIDE + i2;
        float d0 = xs0 - (-1.0f + (float)i0 * interval);
        float d1 = xs1 - (-1.0f + (float)i1 * interval);
        float d2 = xs2 - (-1.0f + (float)i2 * interval);
        d2A[k] = d0 * d0 + d1 * d1 + d2 * d2;
    }
    float svA[8];
    uint4 cuA[8];
    #pragma unroll
    for (int k = 0; k < 8; k++) {
        svA[k] = __ldg(&ks[idxA[k]]);
        cuA[k] = __ldg((const uint4*)(g_lc0h + (idxA[k] << 5)) + c8);
    }

    float acc[8] = {0.f, 0.f, 0.f, 0.f, 0.f, 0.f, 0.f, 0.f};
    float wsum = 0.0f;
    #pragma unroll
    for (int k = 0; k < 8; k++) {
        float phi = 1.0f / (1.0f + d2A[k] * svA[k] * svA[k]);
        wsum += phi;
        float code[8];
        h8tof8(cuA[k], code);
        #pragma unroll
        for (int j = 0; j < 8; j++) acc[j] += phi * code[j];
    }
    float inv = 1.0f / (wsum + 1e-8f);
    float4 bb0 = __ldg(kpb4 + 24 + c8 * 2);
    float4 bb1 = __ldg(kpb4 + 24 + c8 * 2 + 1);
    float4 o0, o1;
    o0.x = acc[0] * inv + bb0.x;
    o0.y = acc[1] * inv + bb0.y;
    o0.z = acc[2] * inv + bb0.z;
    o0.w = acc[3] * inv + bb0.w;
    o1.x = acc[4] * inv + bb1.x;
    o1.y = acc[5] * inv + bb1.y;
    o1.z = acc[6] * inv + bb1.z;
    o1.w = acc[7] * inv + bb1.w;
    float* op = outP + 96 + (c8 << 3);
    __stcs((float4*)op, o0);
    __stcs((float4*)(op + 4), o1);
}

// ------------------------------ launcher ------------------------------------
extern "C" void kernel_launch(void* const* d_in, const int* in_sizes, int n_in,
                              void* d_out, int out_size)
{
    const float* pts  = (const float*)d_in[0];
    const float* aabb = (const float*)d_in[1];
    const float* lc0  = (const float*)d_in[11];
    const float* ks   = (const float*)d_in[12];
    const float* kpb  = (const float*)d_in[13];
    float* out = (float*)d_out;

    int npts = in_sizes[0] / 3;

    // zero histogram via memset node (not a kernel launch)
    void* histPtr = nullptr;
    cudaGetSymbolAddress(&histPtr, g_hist);
    cudaMemsetAsync(histPtr, 0, NBUCK * sizeof(unsigned));

    PrepArgs a;
    for (int i = 0; i < 9; i++) a.p[i] = (const float*)d_in[2 + i];
    a.lc0 = lc0;
    a.pts = pts;
    a.aabb = aabb;
    a.n = npts;

    if (npts <= MAXN) {
        int histBlocks = (npts + 255) / 256;
        prep_kernel<<<16256 + histBlocks, 256>>>(a);   // transpose+lc0+hist
        scan1_kernel<<<32, 1024>>>();
        scatter_kernel<<<(npts + 255) / 256, 256>>>(pts, aabb, npts);
    } else {
        a.n = 0;
        prep_kernel<<<16256, 256>>>(a);
        ident_kernel<<<(npts + 255) / 256, 256>>>(pts, aabb, npts);
    }

    int blocks = (npts + 63) / 64;    // 8 pts/warp * 8 warps
    field_kernel<<<blocks, 256>>>(ks, kpb, out, npts);
}

// round 10
// speedup vs baseline: 1.0580x; 1.0580x over previous
#include <cuda_runtime.h>
#include <cuda_fp16.h>

// ---------------------------------------------------------------------------
// KPlaneRBFField on GB300 — round 10.
//  memset:  g_hist = 0 (graph memset node).
//  k1 prep: transpose 9 planes -> fp16 [r,r,32] + lc0 -> fp16 + Morton hist.
//  k2 scan1, k3 scatter -> sorted (xs0,xs1,xs2,pid).
//  k4 field: 8 pts/warp, __launch_bounds__(256,4) for 50% occ; per-sample
//            MLP=4 loads; x-lerp in HFMA2 (half2), y-lerp fp32; __stcs out.
// ---------------------------------------------------------------------------

#define NSIDE 64
#define MAXN  524288
#define NBUCK 32768
#define TP_POS 128

__device__ __half   g_planesTh[33030144];  // 66 MB transposed fp16 planes
__device__ __half   g_lc0h[8388608];       // 16.5 MB fp16 codes
__device__ unsigned g_hist[NBUCK];
__device__ unsigned g_blksum[32];
__device__ unsigned g_key[MAXN];
__device__ float4   g_spts[MAXN];          // sorted (xs0,xs1,xs2,pid)

__constant__ int c_plane_off[9] = {
    0,        524288,   1048576,
    1572864,  3670016,  5767168,
    7864320,  16252928, 24641536
};
__constant__ int c_blkCum[10] = {0,128,256,384,896,1408,1920,3968,6016,8064};
__constant__ int c_res[9]     = {128,128,128,256,256,256,512,512,512};

struct PrepArgs {
    const float* p[9];
    const float* lc0;
    const float* pts;
    const float* aabb;
    int n;
};

__device__ __forceinline__ unsigned spread3(unsigned x)
{
    x &= 0x3FF;
    x = (x | (x << 16)) & 0x30000FF;
    x = (x | (x << 8))  & 0x300F00F;
    x = (x | (x << 4))  & 0x30C30C3;
    x = (x | (x << 2))  & 0x9249249;
    return x;
}

// ---------------- k1: transpose + lc0 convert + histogram -------------------
__global__ void __launch_bounds__(256) prep_kernel(PrepArgs a)
{
    int b = blockIdx.x;
    int tid = threadIdx.x;

    if (b >= 16256) {                       // Morton histogram
        int i = (b - 16256) * 256 + tid;
        if (i >= a.n) return;
        float a0x = a.aabb[0], a0y = a.aabb[1], a0z = a.aabb[2];
        float a1x = a.aabb[3], a1y = a.aabb[4], a1z = a.aabb[5];
        float x = (a.pts[3 * i + 0] - a0x) * (2.0f / (a1x - a0x)) - 1.0f;
        float y = (a.pts[3 * i + 1] - a0y) * (2.0f / (a1y - a0y)) - 1.0f;
        float z = (a.pts[3 * i + 2] - a0z) * (2.0f / (a1z - a0z)) - 1.0f;
        int qx = min(max((int)((x + 1.0f) * 16.0f), 0), 31);
        int qy = min(max((int)((y + 1.0f) * 16.0f), 0), 31);
        int qz = min(max((int)((z + 1.0f) * 16.0f), 0), 31);
        unsigned key = (spread3(qx) << 2) | (spread3(qy) << 1) | spread3(qz);
        g_key[i] = key;
        atomicAdd(&g_hist[key], 1u);
        return;
    }
    if (b >= 8064) {                        // lc0 convert
        int i = (b - 8064) * 256 + tid;
        float4 v = __ldg((const float4*)a.lc0 + i);
        __half2 h0 = __floats2half2_rn(v.x, v.y);
        __half2 h1 = __floats2half2_rn(v.z, v.w);
        ((uint2*)g_lc0h)[i] = make_uint2(*(unsigned*)&h0, *(unsigned*)&h1);
        return;
    }

    // plane transpose
    __shared__ float tile[TP_POS][33];
    int pi = 0;
    #pragma unroll
    for (int i = 1; i < 9; i++) pi += (b >= c_blkCum[i]) ? 1 : 0;
    int r  = c_res[pi];
    int rr = r * r;
    int posBase = (b - c_blkCum[pi]) * TP_POS;
    const float4* src4 = (const float4*)a.p[pi];
    int rr4 = rr >> 2;
    int pb4 = posBase >> 2;

    #pragma unroll
    for (int it = 0; it < 4; it++) {
        int v  = tid + it * 256;
        int ch = v >> 5;
        int pv = v & 31;
        float4 val = src4[ch * rr4 + pb4 + pv];
        int p = pv << 2;
        tile[p + 0][ch] = val.x;
        tile[p + 1][ch] = val.y;
        tile[p + 2][ch] = val.z;
        tile[p + 3][ch] = val.w;
    }
    __syncthreads();

    uint2* dst2 = (uint2*)(g_planesTh + c_plane_off[pi]) + posBase * 8;
    #pragma unroll
    for (int it = 0; it < 4; it++) {
        int v  = tid + it * 256;
        int p  = v >> 3;
        int c4 = (v & 7) << 2;
        __half2 h0 = __floats2half2_rn(tile[p][c4 + 0], tile[p][c4 + 1]);
        __half2 h1 = __floats2half2_rn(tile[p][c4 + 2], tile[p][c4 + 3]);
        dst2[v] = make_uint2(*(unsigned*)&h0, *(unsigned*)&h1);
    }
}

// ---------------- k2: scan ---------------------------------------------------
__global__ void __launch_bounds__(1024) scan1_kernel()
{
    __shared__ unsigned wsum[32];
    int t = threadIdx.x;
    int lane = t & 31;
    int wid = t >> 5;
    int i = blockIdx.x * 1024 + t;
    unsigned v = g_hist[i];

    unsigned x = v;
    #pragma unroll
    for (int off = 1; off < 32; off <<= 1) {
        unsigned y = __shfl_up_sync(0xFFFFFFFFu, x, off);
        if (lane >= off) x += y;
    }
    if (lane == 31) wsum[wid] = x;
    __syncthreads();
    if (wid == 0) {
        unsigned w = wsum[lane];
        unsigned ww = w;
        #pragma unroll
        for (int off = 1; off < 32; off <<= 1) {
            unsigned y = __shfl_up_sync(0xFFFFFFFFu, ww, off);
            if (lane >= off) ww += y;
        }
        wsum[lane] = ww - w;
        if (lane == 31) g_blksum[blockIdx.x] = ww;
    }
    __syncthreads();
    g_hist[i] = x + wsum[wid] - v;
}

// ---------------- k3: scatter -------------------------------------------------
__global__ void scatter_kernel(const float* __restrict__ pts,
                               const float* __restrict__ aabb, int n)
{
    __shared__ unsigned blkoff[32];
    int t = threadIdx.x;
    if (t < 32) {
        unsigned v = g_blksum[t];
        unsigned x = v;
        #pragma unroll
        for (int off = 1; off < 32; off <<= 1) {
            unsigned y = __shfl_up_sync(0xFFFFFFFFu, x, off);
            if (t >= off) x += y;
        }
        blkoff[t] = x - v;
    }
    __syncthreads();

    int i = blockIdx.x * blockDim.x + t;
    if (i >= n) return;
    unsigned key = g_key[i];
    unsigned pos = atomicAdd(&g_hist[key], 1u) + blkoff[key >> 10];

    float a0x = aabb[0], a0y = aabb[1], a0z = aabb[2];
    float a1x = aabb[3], a1y = aabb[4], a1z = aabb[5];
    float xs0 = (pts[3 * i + 0] - a0x) * (2.0f / (a1x - a0x)) - 1.0f;
    float xs1 = (pts[3 * i + 1] - a0y) * (2.0f / (a1y - a0y)) - 1.0f;
    float xs2 = (pts[3 * i + 2] - a0z) * (2.0f / (a1z - a0z)) - 1.0f;
    g_spts[pos] = make_float4(xs0, xs1, xs2, __int_as_float(i));
}

__global__ void ident_kernel(const float* __restrict__ pts,
                             const float* __restrict__ aabb, int n)
{
    int i = blockIdx.x * blockDim.x + threadIdx.x;
    if (i >= n) return;
    float a0x = aabb[0], a0y = aabb[1], a0z = aabb[2];
    float a1x = aabb[3], a1y = aabb[4], a1z = aabb[5];
    float xs0 = (pts[3 * i + 0] - a0x) * (2.0f / (a1x - a0x)) - 1.0f;
    float xs1 = (pts[3 * i + 1] - a0y) * (2.0f / (a1y - a0y)) - 1.0f;
    float xs2 = (pts[3 * i + 2] - a0z) * (2.0f / (a1z - a0z)) - 1.0f;
    g_spts[i] = make_float4(xs0, xs1, xs2, __int_as_float(i));
}

// ---------------- fp16 helpers ----------------------------------------------
__device__ __forceinline__ void h8tof8(uint4 u, float* f)
{
    float2 p;
    p = __half22float2(*(const __half2*)&u.x); f[0] = p.x; f[1] = p.y;
    p = __half22float2(*(const __half2*)&u.y); f[2] = p.x; f[3] = p.y;
    p = __half22float2(*(const __half2*)&u.z); f[4] = p.x; f[5] = p.y;
    p = __half22float2(*(const __half2*)&u.w); f[6] = p.x; f[7] = p.y;
}

// one bilinear sample of 8 channels: 4 LDG.128 in flight, x-lerp in half2,
// y-lerp in fp32.
__device__ __forceinline__ void sample8(const __half* __restrict__ T, int r,
                                        float u, float v, int c8, float* f)
{
    float fr = (float)(r - 1);
    float fx = (u + 1.0f) * 0.5f * fr;
    float fy = (v + 1.0f) * 0.5f * fr;
    float flx = fminf(fmaxf(floorf(fx), 0.0f), (float)(r - 2));
    float fly = fminf(fmaxf(floorf(fy), 0.0f), (float)(r - 2));
    float wx = fx - flx;
    float wy = fy - fly;
    int ix = (int)flx;
    int iy = (int)fly;
    const uint4* b = (const uint4*)(T + ((iy * r + ix) << 5)) + c8;
    int rs = r << 2;
    uint4 A = __ldg(b);            // (x0,y0) 8ch
    uint4 B = __ldg(b + 4);        // (x1,y0)
    uint4 C = __ldg(b + rs);       // (x0,y1)
    uint4 D = __ldg(b + rs + 4);   // (x1,y1)

    __half2 wx2 = __float2half2_rn(wx);
    const __half2* Ah = (const __half2*)&A;
    const __half2* Bh = (const __half2*)&B;
    const __half2* Ch = (const __half2*)&C;
    const __half2* Dh = (const __half2*)&D;
    #pragma unroll
    for (int i = 0; i < 4; i++) {
        __half2 t = __hfma2(__hsub2(Bh[i], Ah[i]), wx2, Ah[i]);   // top x-lerp
        __half2 o = __hfma2(__hsub2(Dh[i], Ch[i]), wx2, Ch[i]);   // bot x-lerp
        float2 tf = __half22float2(t);
        float2 bf = __half22float2(o);
        f[2 * i + 0] = tf.x + (bf.x - tf.x) * wy;                 // y-lerp fp32
        f[2 * i + 1] = tf.y + (bf.y - tf.y) * wy;
    }
}

// ---------------- k4: field kernel: 8 pts/warp, 50% occ ----------------------
__global__ void __launch_bounds__(256, 4) field_kernel(
    const float* __restrict__ ks,
    const float* __restrict__ kpb,
    float* __restrict__ out,
    int npts)
{
    int gwarp = (int)((blockIdx.x * blockDim.x + threadIdx.x) >> 5);
    int lane  = threadIdx.x & 31;
    int pslot = lane >> 2;
    int c8    = lane & 3;

    int slot = gwarp * 8 + pslot;
    if (slot >= npts) return;

    float4 sp = __ldcs(&g_spts[slot]);     // read-once, streaming
    float xs0 = sp.x, xs1 = sp.y, xs2 = sp.z;
    int pid = __float_as_int(sp.w);

    float* outP = out + (size_t)pid * 128;
    const float4* kpb4 = (const float4*)kpb;

    const int resArr[3] = {128, 256, 512};
    #pragma unroll
    for (int s = 0; s < 3; s++) {
        int r = resArr[s];
        float f0[8], f1[8], f2[8];
        sample8(g_planesTh + c_plane_off[s * 3 + 0], r, xs0, xs1, c8, f0);
        sample8(g_planesTh + c_plane_off[s * 3 + 1], r, xs0, xs2, c8, f1);
        sample8(g_planesTh + c_plane_off[s * 3 + 2], r, xs1, xs2, c8, f2);
        float4 bb0 = __ldg(kpb4 + s * 8 + c8 * 2);
        float4 bb1 = __ldg(kpb4 + s * 8 + c8 * 2 + 1);
        float4 o0, o1;
        o0.x = f0[0] * f1[0] * f2[0] + bb0.x;
        o0.y = f0[1] * f1[1] * f2[1] + bb0.y;
        o0.z = f0[2] * f1[2] * f2[2] + bb0.z;
        o0.w = f0[3] * f1[3] * f2[3] + bb0.w;
        o1.x = f0[4] * f1[4] * f2[4] + bb1.x;
        o1.y = f0[5] * f1[5] * f2[5] + bb1.y;
        o1.z = f0[6] * f1[6] * f2[6] + bb1.z;
        o1.w = f0[7] * f1[7] * f2[7] + bb1.w;
        float* op = outP + s * 32 + (c8 << 3);
        __stcs((float4*)op, o0);
        __stcs((float4*)(op + 4), o1);
    }

    // ---- RBF features over 64^3 grid on [-1,1]
    const float interval = 2.0f / (float)(NSIDE - 1);
    float c0f = fminf(fmaxf(floorf((xs0 + 1.0f) / interval), 0.0f), (float)(NSIDE - 2));
    float c1f = fminf(fmaxf(floorf((xs1 + 1.0f) / interval), 0.0f), (float)(NSIDE - 2));
    float c2f = fminf(fmaxf(floorf((xs2 + 1.0f) / interval), 0.0f), (float)(NSIDE - 2));
    int ci0 = (int)c0f, ci1 = (int)c1f, ci2 = (int)c2f;

    float acc[8] = {0.f, 0.f, 0.f, 0.f, 0.f, 0.f, 0.f, 0.f};
    float wsum = 0.0f;
    // two waves of 4 corners (MLP=4 each) to bound register pressure
    #pragma unroll
    for (int g = 0; g < 2; g++) {
        int idxA[4];
        float d2A[4];
        #pragma unroll
        for (int q = 0; q < 4; q++) {
            int k = g * 4 + q;
            int i0 = ci0 + ((k >> 2) & 1);
            int i1 = ci1 + ((k >> 1) & 1);
            int i2 = ci2 + (k & 1);
            idxA[q] = (i0 * NSIDE + i1) * NSIDE + i2;
            float d0 = xs0 - (-1.0f + (float)i0 * interval);
            float d1 = xs1 - (-1.0f + (float)i1 * interval);
            float d2 = xs2 - (-1.0f + (float)i2 * interval);
            d2A[q] = d0 * d0 + d1 * d1 + d2 * d2;
        }
        float svA[4];
        uint4 cuA[4];
        #pragma unroll
        for (int q = 0; q < 4; q++) {
            svA[q] = __ldg(&ks[idxA[q]]);
            cuA[q] = __ldg((const uint4*)(g_lc0h + (idxA[q] << 5)) + c8);
        }
        #pragma unroll
        for (int q = 0; q < 4; q++) {
            float phi = 1.0f / (1.0f + d2A[q] * svA[q] * svA[q]);
            wsum += phi;
            float code[8];
            h8tof8(cuA[q], code);
            #pragma unroll
            for (int j = 0; j < 8; j++) acc[j] += phi * code[j];
        }
    }
    float inv = 1.0f / (wsum + 1e-8f);
    float4 bb0 = __ldg(kpb4 + 24 + c8 * 2);
    float4 bb1 = __ldg(kpb4 + 24 + c8 * 2 + 1);
    float4 o0, o1;
    o0.x = acc[0] * inv + bb0.x;
    o0.y = acc[1] * inv + bb0.y;
    o0.z = acc[2] * inv + bb0.z;
    o0.w = acc[3] * inv + bb0.w;
    o1.x = acc[4] * inv + bb1.x;
    o1.y = acc[5] * inv + bb1.y;
    o1.z = acc[6] * inv + bb1.z;
    o1.w = acc[7] * inv + bb1.w;
    float* op = outP + 96 + (c8 << 3);
    __stcs((float4*)op, o0);
    __stcs((float4*)(op + 4), o1);
}

// ------------------------------ launcher ------------------------------------
extern "C" void kernel_launch(void* const* d_in, const int* in_sizes, int n_in,
                              void* d_out, int out_size)
{
    const float* pts  = (const float*)d_in[0];
    const float* aabb = (const float*)d_in[1];
    const float* lc0  = (const float*)d_in[11];
    const float* ks   = (const float*)d_in[12];
    const float* kpb  = (const float*)d_in[13];
    float* out = (float*)d_out;

    int npts = in_sizes[0] / 3;

    void* histPtr = nullptr;
    cudaGetSymbolAddress(&histPtr, g_hist);
    cudaMemsetAsync(histPtr, 0, NBUCK * sizeof(unsigned));

    PrepArgs a;
    for (int i = 0; i < 9; i++) a.p[i] = (const float*)d_in[2 + i];
    a.lc0 = lc0;
    a.pts = pts;
    a.aabb = aabb;
    a.n = npts;

    if (npts <= MAXN) {
        int histBlocks = (npts + 255) / 256;
        prep_kernel<<<16256 + histBlocks, 256>>>(a);
        scan1_kernel<<<32, 1024>>>();
        scatter_kernel<<<(npts + 255) / 256, 256>>>(pts, aabb, npts);
    } else {
        a.n = 0;
        prep_kernel<<<16256, 256>>>(a);
        ident_kernel<<<(npts + 255) / 256, 256>>>(pts, aabb, npts);
    }

    int blocks = (npts + 63) / 64;
    field_kernel<<<blocks, 256>>>(ks, kpb, out, npts);
}